// round 5
// baseline (speedup 1.0000x reference)
#include <cuda_runtime.h>
#include <cuda_bf16.h>
#include <cstdint>

// Problem shape (fixed)
#define BB_ 64
#define SS_ 512
#define HH_ 1024
#define LL_ 9

#define TPB 256
#define WARPS 8
#define ROWS_PER_WARP 4
#define ROWS_PER_BLOCK 32
#define NCHUNK 16                 // 512 / 32 mask chunks
#define KC4 32                    // float4 per chunk per row (128 floats)
#define NKC 8                     // k-chunks: 8 * 128 = 1024

// Transposed weights [L][H], written once
__device__ float g_Wt[LL_ * HH_];

typedef unsigned long long u64;

__device__ __forceinline__ u64 fma2(u64 a, u64 b, u64 c) {
    u64 d;
    asm("fma.rn.f32x2 %0, %1, %2, %3;" : "=l"(d) : "l"(a), "l"(b), "l"(c));
    return d;
}
__device__ __forceinline__ u64 add2(u64 a, u64 b) {
    u64 d;
    asm("add.rn.f32x2 %0, %1, %2;" : "=l"(d) : "l"(a), "l"(b));
    return d;
}
__device__ __forceinline__ float pair_sum(u64 v) {
    float lo = __uint_as_float((unsigned)(v & 0xffffffffull));
    float hi = __uint_as_float((unsigned)(v >> 32));
    return lo + hi;
}

__device__ __forceinline__ void cp16(uint32_t dst, const void* src, int srcsize) {
    asm volatile("cp.async.cg.shared.global [%0], [%1], 16, %2;\n"
                 :: "r"(dst), "l"(src), "r"(srcsize));
}
__device__ __forceinline__ void cp_commit() {
    asm volatile("cp.async.commit_group;\n" ::: "memory");
}
template <int N>
__device__ __forceinline__ void cp_wait() {
    asm volatile("cp.async.wait_group %0;\n" :: "n"(N) : "memory");
}

// ---------------------------------------------------------------------------
// One-shot: W [H,L] -> g_Wt [L,H]
// ---------------------------------------------------------------------------
__global__ void transpose_W(const float* __restrict__ W) {
    int j = blockIdx.x;
    int k = threadIdx.x;
    g_Wt[j * HH_ + k] = W[k * LL_ + j];
}

// ---------------------------------------------------------------------------
// Main kernel: block = 32 rows of one batch.
// x streamed via cp.async double buffer (zfill for invalid rows).
// W (transposed) cp.async'd once. Half-warp j-split GEMV with f32x2 FMA.
// ---------------------------------------------------------------------------
extern __shared__ float4 dynsmem[];   // [0,2304): Wt  [2304, 2304+2048): x dbl-buf

__global__ __launch_bounds__(TPB, 2)
void bertner_main_kernel(const float* __restrict__ seq,
                         const int* __restrict__ mask,
                         const float* __restrict__ bias,
                         float* __restrict__ out) {
    float4* sW4 = dynsmem;                     // 9*256 float4 = 36 KB
    float4* xbuf = dynsmem + LL_ * 256;        // 2*32*32 float4 = 32 KB

    __shared__ unsigned mbits[NCHUNK];
    __shared__ int msum[NCHUNK];
    __shared__ int ssrc[ROWS_PER_BLOCK];
    __shared__ int snv;
    __shared__ float sb[LL_];

    int tid  = threadIdx.x;
    int lane = tid & 31;
    int warp = tid >> 5;

    int b  = blockIdx.x >> 4;                  // 16 blocks per batch
    int d0 = (blockIdx.x & 15) * ROWS_PER_BLOCK;

    if (tid < LL_) sb[tid] = bias[tid];

    // ---- per-block mask scan (512 bits) ----
    #pragma unroll
    for (int r = 0; r < 2; r++) {
        int chunk = warp * 2 + r;
        int s = chunk * 32 + lane;
        int m = (mask[b * SS_ + s] != 0);
        unsigned bal = __ballot_sync(0xffffffffu, m);
        if (lane == 0) mbits[chunk] = bal;
    }
    __syncthreads();
    if (tid < NCHUNK) {
        int v = __popc(mbits[tid]);
        #pragma unroll
        for (int off = 1; off < NCHUNK; off <<= 1) {
            int u = __shfl_up_sync(0x0000ffffu, v, off);
            if (tid >= off) v += u;
        }
        msum[tid] = v;
        if (tid == NCHUNK - 1) snv = v;
    }
    __syncthreads();
    int nv = snv;

    if (d0 >= nv) {
        // whole block invalid: softmax(bias) for its 32 rows
        if (tid < ROWS_PER_BLOCK) {
            float l[LL_];
            float mx = -3.402823466e+38f;
            #pragma unroll
            for (int j = 0; j < LL_; j++) { l[j] = sb[j]; mx = fmaxf(mx, l[j]); }
            float ssum = 0.0f;
            #pragma unroll
            for (int j = 0; j < LL_; j++) { l[j] = __expf(l[j] - mx); ssum += l[j]; }
            float inv = __fdividef(1.0f, ssum);
            float* o = out + (size_t)(b * SS_ + d0 + tid) * LL_;
            #pragma unroll
            for (int j = 0; j < LL_; j++) o[j] = l[j] * inv;
        }
        return;
    }

    // ---- source index for each of this block's 32 rows ----
    if (tid < ROWS_PER_BLOCK) {
        int d = d0 + tid;
        int src = 0;
        if (d < nv) {
            int c = 0, base = 0;
            #pragma unroll
            for (int cc = 0; cc < NCHUNK - 1; cc++)
                if (msum[cc] <= d) { c = cc + 1; base = msum[cc]; }
            unsigned wv = mbits[c];
            int rr = d - base;
            for (int t = 0; t < rr; t++) wv &= wv - 1;
            src = c * 32 + (__ffs(wv) - 1);
        }
        ssrc[tid] = src;
    }
    __syncthreads();                            // ssrc ready for cp.async addressing

    uint32_t wbase = (uint32_t)__cvta_generic_to_shared(sW4);
    uint32_t xbase = (uint32_t)__cvta_generic_to_shared(xbuf);
    const float4* seq4 = (const float4*)seq;

    // ---- issue one x chunk (32 rows x 32 float4) into buffer (c&1) ----
    auto issue_chunk = [&](int c) {
        int bufo = (c & 1) * 1024;              // float4 offset
        #pragma unroll
        for (int i = 0; i < 4; i++) {
            int f = i * TPB + tid;              // 0..1023
            int row = f >> 5;
            int k4 = f & 31;
            int sr = ssrc[row];                 // 0 for invalid rows (safe addr)
            int sz = ((d0 + row) < nv) ? 16 : 0;
            const float4* src = seq4 + ((size_t)(b * SS_ + sr) * 256) + c * KC4 + k4;
            cp16(xbase + (uint32_t)(bufo + row * KC4 + k4) * 16u, src, sz);
        }
    };

    // prologue: W + chunk0 as group, then chunk1
    {
        const float4* g = (const float4*)g_Wt;
        #pragma unroll
        for (int i = 0; i < 9; i++)
            cp16(wbase + (uint32_t)(i * TPB + tid) * 16u, g + i * TPB + tid, 16);
    }
    issue_chunk(0);
    cp_commit();
    issue_chunk(1);
    cp_commit();

    // ---- compute mapping ----
    int jg = lane >> 4;                         // 0: j0..3, 1: j4..8
    int kl = lane & 15;
    int jbase = jg * 4;
    int rw0 = warp * ROWS_PER_WARP;

    const ulonglong2* sW2 = (const ulonglong2*)sW4;

    u64 acc[ROWS_PER_WARP][5];
    #pragma unroll
    for (int p = 0; p < ROWS_PER_WARP; p++)
        #pragma unroll
        for (int jj = 0; jj < 5; jj++) acc[p][jj] = 0ull;

    #pragma unroll
    for (int c = 0; c < NKC; c++) {
        if (c == NKC - 1) cp_wait<0>(); else cp_wait<1>();
        __syncthreads();

        const ulonglong2* xc = (const ulonglong2*)(xbuf + (c & 1) * 1024);
        #pragma unroll
        for (int s = 0; s < 2; s++) {
            int k4 = s * 16 + kl;               // chunk-local float4 index
            ulonglong2 xv[ROWS_PER_WARP];
            #pragma unroll
            for (int p = 0; p < ROWS_PER_WARP; p++)
                xv[p] = xc[(rw0 + p) * KC4 + k4];
            int kg = c * KC4 + k4;              // global float4 index
            #pragma unroll
            for (int jj = 0; jj < 5; jj++) {
                if (jj < 4 || jg) {
                    ulonglong2 w = sW2[(jbase + jj) * 256 + kg];
                    #pragma unroll
                    for (int p = 0; p < ROWS_PER_WARP; p++) {
                        acc[p][jj] = fma2(xv[p].x, w.x, acc[p][jj]);
                        acc[p][jj] = fma2(xv[p].y, w.y, acc[p][jj]);
                    }
                }
            }
        }
        __syncthreads();
        if (c + 2 < NKC) { issue_chunk(c + 2); cp_commit(); }
    }

    // ---- reduce over the 16 k-lanes of each half-warp ----
    #pragma unroll
    for (int p = 0; p < ROWS_PER_WARP; p++)
        #pragma unroll
        for (int jj = 0; jj < 5; jj++) {
            u64 a = acc[p][jj];
            #pragma unroll
            for (int off = 8; off >= 1; off >>= 1)
                a = add2(a, __shfl_xor_sync(0xffffffffu, a, off));
            acc[p][jj] = a;
        }

    // ---- epilogue: lane p assembles row p's 9 logits ----
    #pragma unroll
    for (int p = 0; p < ROWS_PER_WARP; p++) {
        float v[5];
        #pragma unroll
        for (int jj = 0; jj < 5; jj++) v[jj] = pair_sum(acc[p][jj]);
        float hi[5];
        #pragma unroll
        for (int jj = 0; jj < 5; jj++)
            hi[jj] = __shfl_xor_sync(0xffffffffu, v[jj], 16);
        if (lane == p) {
            float l[LL_];
            l[0] = v[0]; l[1] = v[1]; l[2] = v[2]; l[3] = v[3];
            l[4] = hi[0]; l[5] = hi[1]; l[6] = hi[2]; l[7] = hi[3]; l[8] = hi[4];
            float mx = -3.402823466e+38f;
            #pragma unroll
            for (int j = 0; j < LL_; j++) { l[j] += sb[j]; mx = fmaxf(mx, l[j]); }
            float ssum = 0.0f;
            #pragma unroll
            for (int j = 0; j < LL_; j++) { l[j] = __expf(l[j] - mx); ssum += l[j]; }
            float inv = __fdividef(1.0f, ssum);
            float* o = out + (size_t)(b * SS_ + d0 + rw0 + p) * LL_;
            #pragma unroll
            for (int j = 0; j < LL_; j++) o[j] = l[j] * inv;
        }
    }
}

// ---------------------------------------------------------------------------
#define DYN_SMEM ((LL_ * 256 + 2 * ROWS_PER_BLOCK * KC4) * 16)   // 69632 B

extern "C" void kernel_launch(void* const* d_in, const int* in_sizes, int n_in,
                              void* d_out, int out_size) {
    const float* seq  = (const float*)d_in[0];   // [B,S,H] f32
    const int*   mask = (const int*)d_in[1];     // [B,S]   i32
    const float* W    = (const float*)d_in[2];   // [H,L]   f32
    const float* bias = (const float*)d_in[3];   // [L]     f32
    float* out = (float*)d_out;                  // [B,S,L] f32

    cudaFuncSetAttribute(bertner_main_kernel,
                         cudaFuncAttributeMaxDynamicSharedMemorySize, DYN_SMEM);

    transpose_W<<<LL_, HH_>>>(W);

    int grid = (BB_ * SS_) / ROWS_PER_BLOCK;     // 1024
    bertner_main_kernel<<<grid, TPB, DYN_SMEM>>>(seq, mask, bias, out);
}

// round 7
// speedup vs baseline: 1.0617x; 1.0617x over previous
#include <cuda_runtime.h>
#include <cuda_bf16.h>
#include <cstdint>

// Problem shape (fixed)
#define BB_ 64
#define SS_ 512
#define HH_ 1024
#define LL_ 9

#define TPB 256
#define WARPS 8
#define ROWS_PER_WARP 4
#define ROWS_PER_BLOCK 32
#define NCHUNK 16                 // 512/32 mask chunks
#define KC4 32                    // float4 per chunk per row (128 floats)
#define NKC 8                     // k-chunks: 8 * 128 = 1024
#define STAGES 4

// Transposed weights [L][H], written once
__device__ float g_Wt[LL_ * HH_];

typedef unsigned long long u64;

__device__ __forceinline__ u64 fma2(u64 a, u64 b, u64 c) {
    u64 d;
    asm("fma.rn.f32x2 %0, %1, %2, %3;" : "=l"(d) : "l"(a), "l"(b), "l"(c));
    return d;
}
__device__ __forceinline__ u64 add2(u64 a, u64 b) {
    u64 d;
    asm("add.rn.f32x2 %0, %1, %2;" : "=l"(d) : "l"(a), "l"(b));
    return d;
}
__device__ __forceinline__ float pair_sum(u64 v) {
    float lo = __uint_as_float((unsigned)(v & 0xffffffffull));
    float hi = __uint_as_float((unsigned)(v >> 32));
    return lo + hi;
}

__device__ __forceinline__ void cp16(uint32_t dst, const void* src, int srcsize) {
    asm volatile("cp.async.cg.shared.global [%0], [%1], 16, %2;\n"
                 :: "r"(dst), "l"(src), "r"(srcsize));
}
__device__ __forceinline__ void cp_commit() {
    asm volatile("cp.async.commit_group;\n" ::: "memory");
}
template <int N>
__device__ __forceinline__ void cp_wait() {
    asm volatile("cp.async.wait_group %0;\n" :: "n"(N) : "memory");
}

// ---------------------------------------------------------------------------
// One-shot: W [H,L] -> g_Wt [L,H]
// ---------------------------------------------------------------------------
__global__ void transpose_W(const float* __restrict__ W) {
    int j = blockIdx.x;
    int k = threadIdx.x;
    g_Wt[j * HH_ + k] = W[k * LL_ + j];
}

// ---------------------------------------------------------------------------
// Main kernel. Block = 32 rows of one batch; each warp owns 4 rows and runs
// its OWN depth-4 cp.async pipeline (per-thread commit groups), no block
// barriers in the hot loop. Half-warp j-split GEMV with f32x2 FMA.
// ---------------------------------------------------------------------------
extern __shared__ float4 dynsmem[];
// layout: [0, 2304)               : Wt as float4 (36 KB)
//         [2304, 2304 + 8*512)    : per-warp x buffers: [warp][stage][row][32] (64 KB)

__global__ __launch_bounds__(TPB, 2)
void bertner_main_kernel(const float* __restrict__ seq,
                         const int* __restrict__ mask,
                         const float* __restrict__ bias,
                         float* __restrict__ out) {
    float4* sW4  = dynsmem;
    float4* xall = dynsmem + LL_ * 256;

    __shared__ unsigned mbits[NCHUNK];
    __shared__ int msum[NCHUNK];
    __shared__ int ssrc[ROWS_PER_BLOCK];
    __shared__ int snv;
    __shared__ float sb[LL_];

    int tid  = threadIdx.x;
    int lane = tid & 31;
    int warp = tid >> 5;

    int b  = blockIdx.x >> 4;
    int d0 = (blockIdx.x & 15) * ROWS_PER_BLOCK;

    if (tid < LL_) sb[tid] = bias[tid];

    // ---- per-block mask scan (512 bits) ----
    #pragma unroll
    for (int r = 0; r < 2; r++) {
        int chunk = warp * 2 + r;
        int s = chunk * 32 + lane;
        int m = (mask[b * SS_ + s] != 0);
        unsigned bal = __ballot_sync(0xffffffffu, m);
        if (lane == 0) mbits[chunk] = bal;
    }
    __syncthreads();
    if (tid < NCHUNK) {
        int v = __popc(mbits[tid]);
        #pragma unroll
        for (int off = 1; off < NCHUNK; off <<= 1) {
            int u = __shfl_up_sync(0x0000ffffu, v, off);
            if (tid >= off) v += u;
        }
        msum[tid] = v;
        if (tid == NCHUNK - 1) snv = v;
    }
    __syncthreads();
    int nv = snv;

    if (d0 >= nv) {
        // whole block invalid: softmax(bias) for its 32 rows
        if (tid < ROWS_PER_BLOCK) {
            float l[LL_];
            float mx = -3.402823466e+38f;
            #pragma unroll
            for (int j = 0; j < LL_; j++) { l[j] = sb[j]; mx = fmaxf(mx, l[j]); }
            float ssum = 0.0f;
            #pragma unroll
            for (int j = 0; j < LL_; j++) { l[j] = __expf(l[j] - mx); ssum += l[j]; }
            float inv = __fdividef(1.0f, ssum);
            float* o = out + (size_t)(b * SS_ + d0 + tid) * LL_;
            #pragma unroll
            for (int j = 0; j < LL_; j++) o[j] = l[j] * inv;
        }
        return;
    }

    // ---- source index for this block's 32 rows ----
    if (tid < ROWS_PER_BLOCK) {
        int d = d0 + tid;
        int src = 0;
        if (d < nv) {
            int c = 0, base = 0;
            #pragma unroll
            for (int cc = 0; cc < NCHUNK - 1; cc++)
                if (msum[cc] <= d) { c = cc + 1; base = msum[cc]; }
            unsigned wv = mbits[c];
            int rr = d - base;
            for (int t = 0; t < rr; t++) wv &= wv - 1;
            src = c * 32 + (__ffs(wv) - 1);
        }
        ssrc[tid] = src;
    }
    __syncthreads();

    // ---- per-warp row info ----
    int rw0 = warp * ROWS_PER_WARP;
    bool vld[ROWS_PER_WARP];
    const float4* xg[ROWS_PER_WARP];
    #pragma unroll
    for (int p = 0; p < ROWS_PER_WARP; p++) {
        int d = d0 + rw0 + p;
        vld[p] = (d < nv);
        xg[p] = (const float4*)seq + ((size_t)(b * SS_ + ssrc[rw0 + p]) * 256);
    }

    uint32_t wbase = (uint32_t)__cvta_generic_to_shared(sW4);
    float4* xw = xall + warp * (STAGES * ROWS_PER_WARP * KC4);   // 512 float4
    uint32_t xwb = (uint32_t)__cvta_generic_to_shared(xw);

    // issue one chunk (4 rows x 32 float4) into stage (c & 3); per-lane: 4 cp16
    auto issue_chunk = [&](int c) {
        int st = (c & (STAGES - 1)) * (ROWS_PER_WARP * KC4);
        #pragma unroll
        for (int p = 0; p < ROWS_PER_WARP; p++) {
            int sz = vld[p] ? 16 : 0;
            cp16(xwb + (uint32_t)(st + p * KC4 + lane) * 16u,
                 xg[p] + c * KC4 + lane, sz);
        }
        cp_commit();
    };

    // prologue: W (group 0) then 4 chunks (groups 1..4)
    {
        const float4* g = (const float4*)g_Wt;
        #pragma unroll
        for (int i = 0; i < 9; i++)
            cp16(wbase + (uint32_t)(i * TPB + tid) * 16u, g + i * TPB + tid, 16);
        cp_commit();
    }
    issue_chunk(0);
    issue_chunk(1);
    issue_chunk(2);
    issue_chunk(3);

    cp_wait<4>();          // W complete
    __syncthreads();       // W visible to all warps

    // ---- compute mapping ----
    int jg = lane >> 4;                     // 0: j0..3, 1: j4..8
    int kl = lane & 15;
    int jbase = jg * 4;
    const ulonglong2* sW2 = (const ulonglong2*)sW4;

    u64 acc[ROWS_PER_WARP][5];
    #pragma unroll
    for (int p = 0; p < ROWS_PER_WARP; p++)
        #pragma unroll
        for (int jj = 0; jj < 5; jj++) acc[p][jj] = 0ull;

    #pragma unroll
    for (int c = 0; c < NKC; c++) {
        // wait for chunk c (tapered at tail); constants fold under full unroll
        if (c == NKC - 3)      cp_wait<2>();
        else if (c == NKC - 2) cp_wait<1>();
        else if (c == NKC - 1) cp_wait<0>();
        else                   cp_wait<3>();
        __syncwarp();

        const ulonglong2* xc =
            (const ulonglong2*)(xw + (c & (STAGES - 1)) * (ROWS_PER_WARP * KC4));
        #pragma unroll
        for (int s = 0; s < 2; s++) {
            int k4 = s * 16 + kl;
            ulonglong2 xv[ROWS_PER_WARP];
            #pragma unroll
            for (int p = 0; p < ROWS_PER_WARP; p++)
                xv[p] = xc[p * KC4 + k4];
            int kg = c * KC4 + k4;
            #pragma unroll
            for (int jj = 0; jj < 5; jj++) {
                if (jj < 4 || jg) {
                    ulonglong2 w = sW2[(jbase + jj) * 256 + kg];
                    #pragma unroll
                    for (int p = 0; p < ROWS_PER_WARP; p++) {
                        acc[p][jj] = fma2(xv[p].x, w.x, acc[p][jj]);
                        acc[p][jj] = fma2(xv[p].y, w.y, acc[p][jj]);
                    }
                }
            }
        }
        __syncwarp();                       // reads done before stage reuse
        if (c + STAGES < NKC) issue_chunk(c + STAGES);
    }

    // ---- reduce over the 16 k-lanes of each half-warp ----
    #pragma unroll
    for (int p = 0; p < ROWS_PER_WARP; p++)
        #pragma unroll
        for (int jj = 0; jj < 5; jj++) {
            u64 a = acc[p][jj];
            #pragma unroll
            for (int off = 8; off >= 1; off >>= 1)
                a = add2(a, __shfl_xor_sync(0xffffffffu, a, off));
            acc[p][jj] = a;
        }

    // ---- epilogue: lane p assembles row p's 9 logits ----
    #pragma unroll
    for (int p = 0; p < ROWS_PER_WARP; p++) {
        float v[5];
        #pragma unroll
        for (int jj = 0; jj < 5; jj++) v[jj] = pair_sum(acc[p][jj]);
        float hi[5];
        #pragma unroll
        for (int jj = 0; jj < 5; jj++)
            hi[jj] = __shfl_xor_sync(0xffffffffu, v[jj], 16);
        if (lane == p) {
            float l[LL_];
            l[0] = v[0]; l[1] = v[1]; l[2] = v[2]; l[3] = v[3];
            l[4] = hi[0]; l[5] = hi[1]; l[6] = hi[2]; l[7] = hi[3]; l[8] = hi[4];
            float mx = -3.402823466e+38f;
            #pragma unroll
            for (int j = 0; j < LL_; j++) { l[j] += sb[j]; mx = fmaxf(mx, l[j]); }
            float ssum = 0.0f;
            #pragma unroll
            for (int j = 0; j < LL_; j++) { l[j] = __expf(l[j] - mx); ssum += l[j]; }
            float inv = __fdividef(1.0f, ssum);
            float* o = out + (size_t)(b * SS_ + d0 + rw0 + p) * LL_;
            #pragma unroll
            for (int j = 0; j < LL_; j++) o[j] = l[j] * inv;
        }
    }
}

// ---------------------------------------------------------------------------
#define DYN_SMEM ((LL_ * 256 + WARPS * STAGES * ROWS_PER_WARP * KC4) * 16)  // 102400 B

extern "C" void kernel_launch(void* const* d_in, const int* in_sizes, int n_in,
                              void* d_out, int out_size) {
    const float* seq  = (const float*)d_in[0];   // [B,S,H] f32
    const int*   mask = (const int*)d_in[1];     // [B,S]   i32
    const float* W    = (const float*)d_in[2];   // [H,L]   f32
    const float* bias = (const float*)d_in[3];   // [L]     f32
    float* out = (float*)d_out;                  // [B,S,L] f32

    cudaFuncSetAttribute(bertner_main_kernel,
                         cudaFuncAttributeMaxDynamicSharedMemorySize, DYN_SMEM);

    transpose_W<<<LL_, HH_>>>(W);

    int grid = (BB_ * SS_) / ROWS_PER_BLOCK;     // 1024
    bertner_main_kernel<<<grid, TPB, DYN_SMEM>>>(seq, mask, bias, out);
}